// round 3
// baseline (speedup 1.0000x reference)
#include <cuda_runtime.h>
#include <cstdint>
#include <math.h>

#define NEURONS 4096
#define HIST    64
#define MID     128
#define BATCH   1024
#define TILE_M  128
#define NTILES  (BATCH / TILE_M)

#define XS_STRIDE  68    // words; A-frag LDS conflict-free (round-1 verified)
#define W1S_STRIDE 136   // words; only used once for B-frag hoist

// dynamic smem layout (bytes)
#define XBUF_BYTES (TILE_M * XS_STRIDE * 4)          // 34816
#define OFF_X   0                                    // 2 buffers
#define OFF_W1  (2 * XBUF_BYTES)                     // 69632
#define OFF_W2  (OFF_W1 + HIST * W1S_STRIDE * 4)     // 104448
#define OFF_RED (OFF_W2 + 512)                       // 104960
#define SMEM_TOTAL (OFF_RED + 4 * TILE_M * 4)        // 107008

__device__ __forceinline__ uint32_t smem_u32(const void* p) {
    uint32_t a;
    asm("{ .reg .u64 t; cvta.to.shared.u64 t, %1; cvt.u32.u64 %0, t; }" : "=r"(a) : "l"(p));
    return a;
}
__device__ __forceinline__ uint32_t f2tf32(float f) {
    uint32_t r; asm("cvt.rna.tf32.f32 %0, %1;" : "=r"(r) : "f"(f)); return r;
}
__device__ __forceinline__ void cp_async16(uint32_t smem_addr, const void* gptr) {
    asm volatile("cp.async.cg.shared.global [%0], [%1], 16;"
                 :: "r"(smem_addr), "l"(gptr) : "memory");
}
__device__ __forceinline__ void cp_commit() {
    asm volatile("cp.async.commit_group;" ::: "memory");
}
template<int N> __device__ __forceinline__ void cp_wait() {
    asm volatile("cp.async.wait_group %0;" :: "n"(N) : "memory");
}
__device__ __forceinline__ float gelu_exact(float v) {
    return 0.5f * v * (1.0f + erff(v * 0.70710678118654752f));
}

extern "C" __global__ void __launch_bounds__(256, 1)
neuron_mlp_v3(const float* __restrict__ x,
              const float* __restrict__ w1,
              const float* __restrict__ w2,
              float* __restrict__ out)
{
    extern __shared__ unsigned char sm[];
    const uint32_t smem_base = smem_u32(sm);
    float*    Xs  = (float*)(sm + OFF_X);        // 2 x [128][68] raw f32
    uint32_t* W1s = (uint32_t*)(sm + OFF_W1);    // [64][136] tf32
    float*    W2s = (float*)(sm + OFF_W2);       // [128]
    float*    red = (float*)(sm + OFF_RED);      // [4][128]

    const int tid  = threadIdx.x;
    const int wid  = tid >> 5;
    const int lane = tid & 31;
    const int n    = blockIdx.x;

    // ---- stage w1 [64][128] -> W1s (tf32), once per neuron ----
    {
        const int q   = tid & 3;
        const int row = tid >> 2;  // 0..63
        const float4* src = (const float4*)(w1 + (size_t)n * (HIST * MID) + (size_t)row * MID);
        uint32_t* dst = W1s + row * W1S_STRIDE;
        #pragma unroll
        for (int i = 0; i < 8; ++i) {
            float4 v = src[i * 4 + q];
            const int c = (i * 4 + q) * 4;
            dst[c + 0] = f2tf32(v.x); dst[c + 1] = f2tf32(v.y);
            dst[c + 2] = f2tf32(v.z); dst[c + 3] = f2tf32(v.w);
        }
    }
    if (tid < MID) W2s[tid] = w2[(size_t)n * MID + tid];
    __syncthreads();

    const int warp_m = wid & 1;    // 2 warps along M (64 rows each)
    const int warp_n = wid >> 1;   // 4 warps along N (32 cols each)
    const int r = lane >> 2;
    const int q = lane & 3;
    const int n0 = warp_n * 32;

    // ---- hoist persistent B fragments (64 regs) and w2 (8 regs) ----
    uint32_t breg[4][8][2];
    #pragma unroll
    for (int nt = 0; nt < 4; ++nt)
        #pragma unroll
        for (int k = 0; k < 8; ++k) {
            breg[nt][k][0] = W1s[(k * 8 + q)     * W1S_STRIDE + n0 + nt * 8 + r];
            breg[nt][k][1] = W1s[(k * 8 + q + 4) * W1S_STRIDE + n0 + nt * 8 + r];
        }
    float w2r[4][2];
    #pragma unroll
    for (int nt = 0; nt < 4; ++nt) {
        const int c = n0 + nt * 8 + 2 * q;
        w2r[nt][0] = W2s[c]; w2r[nt][1] = W2s[c + 1];
    }

    // A-tile cp.async indexing: thread covers row = tid>>1, chunks (tid&1)*8 + i
    const int ld_row = tid >> 1;
    const int ld_c0  = (tid & 1) * 8;

    // ---- prologue: async-load tile 0 ----
    {
        const float* src = x + (size_t)ld_row * (NEURONS * HIST) + (size_t)n * HIST;
        const uint32_t dst = smem_base + OFF_X + (ld_row * XS_STRIDE) * 4;
        #pragma unroll
        for (int i = 0; i < 8; ++i)
            cp_async16(dst + (ld_c0 + i) * 16, src + (ld_c0 + i) * 4);
        cp_commit();
    }

    for (int t = 0; t < NTILES; ++t) {
        // issue next tile's loads, then wait for current tile
        if (t < NTILES - 1) {
            const int b1 = (t + 1) * TILE_M;
            const float* src = x + (size_t)(b1 + ld_row) * (NEURONS * HIST) + (size_t)n * HIST;
            const uint32_t dst = smem_base + OFF_X + ((t + 1) & 1) * XBUF_BYTES
                               + (ld_row * XS_STRIDE) * 4;
            #pragma unroll
            for (int i = 0; i < 8; ++i)
                cp_async16(dst + (ld_c0 + i) * 16, src + (ld_c0 + i) * 4);
            cp_commit();
            cp_wait<1>();
        } else {
            cp_wait<0>();
        }
        __syncthreads();

        const float* Ab = Xs + (t & 1) * (XBUF_BYTES / 4);

        float acc[4][4][4];
        #pragma unroll
        for (int mt = 0; mt < 4; ++mt)
            #pragma unroll
            for (int nt = 0; nt < 4; ++nt)
                #pragma unroll
                for (int j = 0; j < 4; ++j) acc[mt][nt][j] = 0.f;

        #pragma unroll
        for (int k = 0; k < 8; ++k) {
            const int kk = k * 8;
            uint32_t a[4][4];
            #pragma unroll
            for (int mt = 0; mt < 4; ++mt) {
                const int m0 = warp_m * 64 + mt * 16;
                a[mt][0] = f2tf32(Ab[(m0 + r)     * XS_STRIDE + kk + q]);
                a[mt][1] = f2tf32(Ab[(m0 + r + 8) * XS_STRIDE + kk + q]);
                a[mt][2] = f2tf32(Ab[(m0 + r)     * XS_STRIDE + kk + q + 4]);
                a[mt][3] = f2tf32(Ab[(m0 + r + 8) * XS_STRIDE + kk + q + 4]);
            }
            #pragma unroll
            for (int mt = 0; mt < 4; ++mt)
                #pragma unroll
                for (int nt = 0; nt < 4; ++nt) {
                    asm volatile(
                        "mma.sync.aligned.m16n8k8.row.col.f32.tf32.tf32.f32 "
                        "{%0,%1,%2,%3}, {%4,%5,%6,%7}, {%8,%9}, {%0,%1,%2,%3};"
                        : "+f"(acc[mt][nt][0]), "+f"(acc[mt][nt][1]),
                          "+f"(acc[mt][nt][2]), "+f"(acc[mt][nt][3])
                        : "r"(a[mt][0]), "r"(a[mt][1]), "r"(a[mt][2]), "r"(a[mt][3]),
                          "r"(breg[nt][k][0]), "r"(breg[nt][k][1]));
                }
        }

        // ---- epilogue: exact GELU, fold w2, reduce over MID ----
        #pragma unroll
        for (int mt = 0; mt < 4; ++mt) {
            float s0 = 0.f, s1 = 0.f;
            #pragma unroll
            for (int nt = 0; nt < 4; ++nt) {
                s0 += gelu_exact(acc[mt][nt][0]) * w2r[nt][0]
                    + gelu_exact(acc[mt][nt][1]) * w2r[nt][1];
                s1 += gelu_exact(acc[mt][nt][2]) * w2r[nt][0]
                    + gelu_exact(acc[mt][nt][3]) * w2r[nt][1];
            }
            s0 += __shfl_xor_sync(0xffffffffu, s0, 1);
            s0 += __shfl_xor_sync(0xffffffffu, s0, 2);
            s1 += __shfl_xor_sync(0xffffffffu, s1, 1);
            s1 += __shfl_xor_sync(0xffffffffu, s1, 2);
            if (q == 0) {
                const int row = warp_m * 64 + mt * 16 + r;
                red[warp_n * TILE_M + row]     = s0;
                red[warp_n * TILE_M + row + 8] = s1;
            }
        }
        __syncthreads();
        if (tid < TILE_M) {
            out[(size_t)(t * TILE_M + tid) * NEURONS + n] =
                red[tid] + red[TILE_M + tid] + red[2 * TILE_M + tid] + red[3 * TILE_M + tid];
        }
        // next iteration's __syncthreads() (after cp_wait) protects red + A-buffer reuse
    }
}

extern "C" void kernel_launch(void* const* d_in, const int* in_sizes, int n_in,
                              void* d_out, int out_size) {
    const float* x  = (const float*)d_in[0];
    const float* w1 = (const float*)d_in[1];
    const float* w2 = (const float*)d_in[2];
    float* out = (float*)d_out;

    cudaFuncSetAttribute(neuron_mlp_v3,
                         cudaFuncAttributeMaxDynamicSharedMemorySize, SMEM_TOTAL);
    neuron_mlp_v3<<<NEURONS, 256, SMEM_TOTAL>>>(x, w1, w2, out);
}